// round 2
// baseline (speedup 1.0000x reference)
#include <cuda_runtime.h>
#include <cuda_bf16.h>
#include <cstdint>

// Problem constants
#define B_ 16
#define T_ 16384
#define D_ 256
#define S_ 4
#define TILE 128
#define KT 64
#define KSPLIT 8
#define KCHUNK (T_ / KSPLIT)   // 2048
#define PITCH 136              // 128 + 8 pad -> conflict-free ldmatrix.trans
#define MS (KT * PITCH)        // elements per smem matrix stage

// Scratch (device globals: allocation-free rule)
__device__ __nv_bfloat16 g_V[(size_t)B_ * T_ * D_];       // normalized V, bf16
__device__ unsigned char g_cls[B_ * T_];                   // speaker class per row
__device__ float g_GvvP[(size_t)48 * KSPLIT * TILE * TILE]; // K-split partials
__device__ float g_Gvy[B_ * D_ * S_];
__device__ float g_part[64];

// ---------------------------------------------------------------------------
// K1: row-wise L2 normalize fp32 -> bf16, extract class index from one-hot
// ---------------------------------------------------------------------------
__global__ __launch_bounds__(256) void k_norm(const float* __restrict__ emb,
                                              const float* __restrict__ lab) {
    int row  = blockIdx.x * 8 + (threadIdx.x >> 5);
    int lane = threadIdx.x & 31;
    const float4* src = reinterpret_cast<const float4*>(emb) + (size_t)row * (D_ / 4) + lane * 2;
    float4 v0 = src[0];
    float4 v1 = src[1];
    float ss = v0.x*v0.x + v0.y*v0.y + v0.z*v0.z + v0.w*v0.w
             + v1.x*v1.x + v1.y*v1.y + v1.z*v1.z + v1.w*v1.w;
    #pragma unroll
    for (int o = 16; o; o >>= 1) ss += __shfl_xor_sync(0xffffffffu, ss, o);
    float sc = 1.0f / fmaxf(sqrtf(ss), 1e-12f);

    __nv_bfloat162 p0 = __floats2bfloat162_rn(v0.x * sc, v0.y * sc);
    __nv_bfloat162 p1 = __floats2bfloat162_rn(v0.z * sc, v0.w * sc);
    __nv_bfloat162 p2 = __floats2bfloat162_rn(v1.x * sc, v1.y * sc);
    __nv_bfloat162 p3 = __floats2bfloat162_rn(v1.z * sc, v1.w * sc);
    uint4 pk;
    pk.x = *reinterpret_cast<uint32_t*>(&p0);
    pk.y = *reinterpret_cast<uint32_t*>(&p1);
    pk.z = *reinterpret_cast<uint32_t*>(&p2);
    pk.w = *reinterpret_cast<uint32_t*>(&p3);
    reinterpret_cast<uint4*>(g_V)[(size_t)row * (D_ / 8) + lane] = pk;

    if (lane == 0) {
        float4 lb = reinterpret_cast<const float4*>(lab)[row];
        g_cls[row] = lb.y > 0.5f ? 1 : (lb.z > 0.5f ? 2 : (lb.w > 0.5f ? 3 : 0));
    }
}

// ---------------------------------------------------------------------------
// K0: zero only the Gvy atomic target (16K floats)
// ---------------------------------------------------------------------------
__global__ void k_zero() {
    int i = blockIdx.x * 256 + threadIdx.x;
    if (i < B_ * D_ * S_) g_Gvy[i] = 0.0f;
}

// ---------------------------------------------------------------------------
// PTX helpers
// ---------------------------------------------------------------------------
__device__ __forceinline__ void cp16(__nv_bfloat16* dst, const __nv_bfloat16* src) {
    unsigned d = (unsigned)__cvta_generic_to_shared(dst);
    asm volatile("cp.async.cg.shared.global [%0], [%1], 16;\n" :: "r"(d), "l"(src));
}
__device__ __forceinline__ void cp_commit() { asm volatile("cp.async.commit_group;\n"); }
template <int N> __device__ __forceinline__ void cp_wait() {
    asm volatile("cp.async.wait_group %0;\n" :: "n"(N));
}
__device__ __forceinline__ void ldsm4t(uint32_t* r, const __nv_bfloat16* p) {
    unsigned a = (unsigned)__cvta_generic_to_shared(p);
    asm volatile("ldmatrix.sync.aligned.m8n8.x4.trans.shared.b16 {%0,%1,%2,%3}, [%4];\n"
                 : "=r"(r[0]), "=r"(r[1]), "=r"(r[2]), "=r"(r[3]) : "r"(a));
}
__device__ __forceinline__ void mma_bf16(float* c, const uint32_t* a, const uint32_t* b) {
    asm volatile("mma.sync.aligned.m16n8k16.row.col.f32.bf16.bf16.f32 "
                 "{%0,%1,%2,%3},{%4,%5,%6,%7},{%8,%9},{%0,%1,%2,%3};\n"
                 : "+f"(c[0]), "+f"(c[1]), "+f"(c[2]), "+f"(c[3])
                 : "r"(a[0]), "r"(a[1]), "r"(a[2]), "r"(a[3]), "r"(b[0]), "r"(b[1]));
}

// ---------------------------------------------------------------------------
// K2: Gram tiles Gvv = V^T V. grid.x = 48 (batch*3 + tile), grid.y = KSPLIT.
// Epilogue now writes K-split partials with plain stores (no atomics).
// ---------------------------------------------------------------------------
__global__ __launch_bounds__(256) void k_gram() {
    extern __shared__ __nv_bfloat16 sm[];
    int bt   = blockIdx.x;
    int b    = bt / 3, tile = bt % 3;
    int ti   = (tile == 0) ? 0 : 1;
    int tj   = (tile == 2) ? 1 : 0;
    bool diag = (ti == tj);
    int kc   = blockIdx.y;
    int tid  = threadIdx.x;
    const __nv_bfloat16* gv = g_V + (size_t)(b * T_ + kc * KCHUNK) * D_;

    int wid = tid >> 5, lane = tid & 31;
    int wm = (wid & 3) * 32;
    int wn = (wid >> 2) * 64;
    int q = lane >> 3, rr = lane & 7;

    float acc[2][8][4];
    #pragma unroll
    for (int mi = 0; mi < 2; mi++)
        #pragma unroll
        for (int ni = 0; ni < 8; ni++)
            #pragma unroll
            for (int x = 0; x < 4; x++) acc[mi][ni][x] = 0.0f;

    auto load_stage = [&](int st, int kofs) {
        const __nv_bfloat16* ga = gv + (size_t)kofs * D_ + ti * TILE;
        __nv_bfloat16* sa = sm + st * MS;
        #pragma unroll
        for (int i = 0; i < 4; i++) {
            int c = tid + i * 256;
            int r = c >> 4, cc = c & 15;
            cp16(sa + r * PITCH + cc * 8, ga + r * D_ + cc * 8);
        }
        if (!diag) {
            const __nv_bfloat16* gb = gv + (size_t)kofs * D_ + tj * TILE;
            __nv_bfloat16* sb = sm + (2 + st) * MS;
            #pragma unroll
            for (int i = 0; i < 4; i++) {
                int c = tid + i * 256;
                int r = c >> 4, cc = c & 15;
                cp16(sb + r * PITCH + cc * 8, gb + r * D_ + cc * 8);
            }
        }
        cp_commit();
    };

    load_stage(0, 0);
    const int NIT = KCHUNK / KT;  // 32
    for (int it = 0; it < NIT; ++it) {
        if (it + 1 < NIT) { load_stage((it + 1) & 1, (it + 1) * KT); cp_wait<1>(); }
        else              { cp_wait<0>(); }
        __syncthreads();
        const __nv_bfloat16* As = sm + (it & 1) * MS;
        const __nv_bfloat16* Bs = diag ? As : sm + (2 + (it & 1)) * MS;
        #pragma unroll
        for (int ks = 0; ks < KT / 16; ++ks) {
            uint32_t af[2][4];
            #pragma unroll
            for (int mi = 0; mi < 2; mi++) {
                int dm   = wm + mi * 16;
                int krow = ks * 16 + ((q & 2) ? 8 : 0) + rr;
                int col  = dm + ((q & 1) ? 8 : 0);
                ldsm4t(af[mi], As + krow * PITCH + col);
            }
            uint32_t bfr[8][2];
            #pragma unroll
            for (int j = 0; j < 4; j++) {
                int n0   = wn + j * 16;
                int krow = ks * 16 + ((q & 1) ? 8 : 0) + rr;
                int col  = n0 + ((q & 2) ? 8 : 0);
                uint32_t t4[4];
                ldsm4t(t4, Bs + krow * PITCH + col);
                bfr[2 * j][0]     = t4[0]; bfr[2 * j][1]     = t4[1];
                bfr[2 * j + 1][0] = t4[2]; bfr[2 * j + 1][1] = t4[3];
            }
            #pragma unroll
            for (int mi = 0; mi < 2; mi++)
                #pragma unroll
                for (int ni = 0; ni < 8; ni++)
                    mma_bf16(acc[mi][ni], af[mi], bfr[ni]);
        }
        __syncthreads();
    }

    // Epilogue: plain stores of this K-split's partial tile
    int gid = lane >> 2, tig = lane & 3;
    float* gdst = g_GvvP + ((size_t)bt * KSPLIT + kc) * TILE * TILE;
    #pragma unroll
    for (int mi = 0; mi < 2; mi++) {
        #pragma unroll
        for (int ni = 0; ni < 8; ni++) {
            int m = wm + mi * 16 + gid;
            int n = wn + ni * 8 + tig * 2;
            float* p = gdst + m * TILE + n;
            p[0] = acc[mi][ni][0];
            p[1] = acc[mi][ni][1];
            p[8 * TILE + 0] = acc[mi][ni][2];
            p[8 * TILE + 1] = acc[mi][ni][3];
        }
    }
}

// ---------------------------------------------------------------------------
// K3: Gvy[b][d][s] = per-class column sums. Warp-per-row, vectorized.
// grid = B_ * 16 chunks (1024 rows each); 8 warps/CTA, warp strides rows by 8,
// unrolled x4 for MLP. Cross-warp smem reduce, then sparse global atomics.
// ---------------------------------------------------------------------------
__global__ __launch_bounds__(256) void k_gvy() {
    __shared__ float sred[8 * 1024];
    int b   = blockIdx.x >> 4;
    int ch  = blockIdx.x & 15;
    int wid = threadIdx.x >> 5, lane = threadIdx.x & 31;
    const uint4* vb = reinterpret_cast<const uint4*>(g_V) + (size_t)b * T_ * (D_ / 8);
    const unsigned char* cb = g_cls + b * T_;

    float acc[4][8];
    #pragma unroll
    for (int c = 0; c < 4; c++)
        #pragma unroll
        for (int i = 0; i < 8; i++) acc[c][i] = 0.0f;

    auto proc = [&](uint4 pk, int s) {
        float2 f0 = __bfloat1622float2(*reinterpret_cast<__nv_bfloat162*>(&pk.x));
        float2 f1 = __bfloat1622float2(*reinterpret_cast<__nv_bfloat162*>(&pk.y));
        float2 f2 = __bfloat1622float2(*reinterpret_cast<__nv_bfloat162*>(&pk.z));
        float2 f3 = __bfloat1622float2(*reinterpret_cast<__nv_bfloat162*>(&pk.w));
        float* a = acc[0];
        if (s == 1) a = acc[1]; else if (s == 2) a = acc[2]; else if (s == 3) a = acc[3];
        a[0] += f0.x; a[1] += f0.y; a[2] += f1.x; a[3] += f1.y;
        a[4] += f2.x; a[5] += f2.y; a[6] += f3.x; a[7] += f3.y;
    };

    int tbase = ch * 1024 + wid;
    #pragma unroll 1
    for (int k = 0; k < 128; k += 4) {
        int t = tbase + 8 * k;
        uint4 p0 = vb[(size_t)(t +  0) * 32 + lane];
        uint4 p1 = vb[(size_t)(t +  8) * 32 + lane];
        uint4 p2 = vb[(size_t)(t + 16) * 32 + lane];
        uint4 p3 = vb[(size_t)(t + 24) * 32 + lane];
        int s0 = cb[t]; int s1 = cb[t + 8]; int s2 = cb[t + 16]; int s3 = cb[t + 24];
        proc(p0, s0); proc(p1, s1); proc(p2, s2); proc(p3, s3);
    }

    // smem layout: [wid][v*32 + lane], v = c*8 + i  (conflict-free both phases)
    #pragma unroll
    for (int c = 0; c < 4; c++)
        #pragma unroll
        for (int i = 0; i < 8; i++)
            sred[wid * 1024 + (c * 8 + i) * 32 + lane] = acc[c][i];
    __syncthreads();

    #pragma unroll
    for (int j = 0; j < 4; j++) {
        int o = threadIdx.x + 256 * j;   // o = v*32 + l
        float sum = 0.0f;
        #pragma unroll
        for (int w = 0; w < 8; w++) sum += sred[w * 1024 + o];
        int v = o >> 5, l = o & 31;
        int d = l * 8 + (v & 7), s = v >> 3;
        atomicAdd(g_Gvy + (b * D_ + d) * S_ + s, sum);
    }
}

// ---------------------------------------------------------------------------
// Reductions
// ---------------------------------------------------------------------------
__device__ float blockSum(float v) {
    __shared__ float sw[8];
    int lane = threadIdx.x & 31, w = threadIdx.x >> 5;
    __syncthreads();
    #pragma unroll
    for (int o = 16; o; o >>= 1) v += __shfl_xor_sync(0xffffffffu, v, o);
    if (lane == 0) sw[w] = v;
    __syncthreads();
    v = (threadIdx.x < 8) ? sw[threadIdx.x] : 0.0f;
    if (w == 0)
        #pragma unroll
        for (int o = 4; o; o >>= 1) v += __shfl_xor_sync(0xffu, v, o);
    return v;  // valid in thread 0
}

__global__ __launch_bounds__(256) void k_red1() {
    int bid = blockIdx.x, tid = threadIdx.x;
    if (bid < 48) {
        const float* g = g_GvvP + (size_t)bid * KSPLIT * TILE * TILE;
        float total = 0.0f;
        for (int i = tid; i < TILE * TILE; i += 256) {
            float x = 0.0f;
            #pragma unroll
            for (int kc = 0; kc < KSPLIT; kc++) x += g[kc * TILE * TILE + i];
            total += x * x;
        }
        total = blockSum(total);
        if (tid == 0) {
            float w = (bid % 3 == 1) ? 2.0f : 1.0f;  // off-diagonal tile counts twice
            g_part[bid] = w * total;
        }
    } else {
        int b = bid - 48;
        float gy = 0.0f;
        for (int i = tid; i < D_ * S_; i += 256) { float x = g_Gvy[b * D_ * S_ + i]; gy += x * x; }
        float c0 = 0, c1 = 0, c2 = 0, c3 = 0;
        for (int t = tid; t < T_; t += 256) {
            int s = g_cls[b * T_ + t];
            c0 += (s == 0); c1 += (s == 1); c2 += (s == 2); c3 += (s == 3);
        }
        gy = blockSum(gy);
        c0 = blockSum(c0); c1 = blockSum(c1); c2 = blockSum(c2); c3 = blockSum(c3);
        if (tid == 0)
            g_part[bid] = -2.0f * gy + c0 * c0 + c1 * c1 + c2 * c2 + c3 * c3;
    }
}

__global__ void k_final(float* out) {
    int tid = threadIdx.x;  // 64 threads
    float v = g_part[tid];
    #pragma unroll
    for (int o = 16; o; o >>= 1) v += __shfl_xor_sync(0xffffffffu, v, o);
    __shared__ float s2[2];
    if ((tid & 31) == 0) s2[tid >> 5] = v;
    __syncthreads();
    if (tid == 0) {
        float total = s2[0] + s2[1];
        // divide by T*T*B = 2^32 (exact power of two)
        out[0] = total * 2.3283064365386963e-10f;
    }
}

// ---------------------------------------------------------------------------
extern "C" void kernel_launch(void* const* d_in, const int* in_sizes, int n_in,
                              void* d_out, int out_size) {
    const float* emb = (const float*)d_in[0];
    const float* lab = (const float*)d_in[1];
    float* out = (float*)d_out;
    (void)in_sizes; (void)n_in; (void)out_size;

    const int smem_bytes = 4 * MS * (int)sizeof(__nv_bfloat16);  // 69632
    cudaFuncSetAttribute(k_gram, cudaFuncAttributeMaxDynamicSharedMemorySize, smem_bytes);

    k_zero<<<64, 256>>>();
    k_norm<<<(B_ * T_) / 8, 256>>>(emb, lab);
    dim3 g2(48, KSPLIT);
    k_gram<<<g2, 256, smem_bytes>>>();
    k_gvy<<<B_ * 16, 256>>>();
    k_red1<<<64, 256>>>();
    k_final<<<1, 64>>>(out);
}

// round 3
// speedup vs baseline: 1.8455x; 1.8455x over previous
#include <cuda_runtime.h>
#include <cuda_bf16.h>
#include <cstdint>

// Problem constants
#define B_ 16
#define T_ 16384
#define D_ 256
#define S_ 4
#define TILE 128
#define KT 64
#define KSPLIT 8
#define KCHUNK (T_ / KSPLIT)   // 2048
#define PITCH 136              // 128 + 8 pad -> conflict-free ldmatrix.trans
#define MS (KT * PITCH)        // elements per smem matrix stage

// Scratch (device globals: allocation-free rule)
__device__ __nv_bfloat16 g_V[(size_t)B_ * T_ * D_];         // normalized V, bf16
__device__ unsigned char g_cls[B_ * T_];                     // speaker class per row
__device__ float g_GvvP[(size_t)48 * KSPLIT * TILE * TILE];  // K-split partials
__device__ float g_Gvy[B_ * D_ * S_];
__device__ float g_part[64];

// ---------------------------------------------------------------------------
// K0: zero the Gvy atomic target
// ---------------------------------------------------------------------------
__global__ void k_zero() {
    int i = blockIdx.x * 256 + threadIdx.x;
    if (i < B_ * D_ * S_) g_Gvy[i] = 0.0f;
}

// ---------------------------------------------------------------------------
// K1: fused row-wise L2 normalize (fp32 -> bf16) + class extraction + Gvy
// accumulation. 512 blocks (32 per batch), 8 warps, warp = 64 consecutive
// rows. Class accumulators are STATIC-indexed registers (uniform branch per
// row) -- no dynamic indexing, no spill.
// ---------------------------------------------------------------------------
__global__ __launch_bounds__(256) void k_norm(const float* __restrict__ emb,
                                              const float* __restrict__ lab) {
    __shared__ float sred[8 * 1024];
    int b    = blockIdx.x >> 5;
    int ch   = blockIdx.x & 31;
    int wid  = threadIdx.x >> 5, lane = threadIdx.x & 31;
    int row0 = b * T_ + ch * 512 + wid * 64;

    float acc[4][8];
    #pragma unroll
    for (int c = 0; c < 4; c++)
        #pragma unroll
        for (int i = 0; i < 8; i++) acc[c][i] = 0.0f;

    #pragma unroll 2
    for (int r = 0; r < 64; ++r) {
        int row = row0 + r;
        const float4* src = reinterpret_cast<const float4*>(emb) + (size_t)row * (D_ / 4) + lane * 2;
        float4 v0 = src[0];
        float4 v1 = src[1];
        float ss = v0.x*v0.x + v0.y*v0.y + v0.z*v0.z + v0.w*v0.w
                 + v1.x*v1.x + v1.y*v1.y + v1.z*v1.z + v1.w*v1.w;
        #pragma unroll
        for (int o = 16; o; o >>= 1) ss += __shfl_xor_sync(0xffffffffu, ss, o);
        float sc = 1.0f / fmaxf(sqrtf(ss), 1e-12f);

        float n0 = v0.x * sc, n1 = v0.y * sc, n2 = v0.z * sc, n3 = v0.w * sc;
        float n4 = v1.x * sc, n5 = v1.y * sc, n6 = v1.z * sc, n7 = v1.w * sc;

        __nv_bfloat162 p0 = __floats2bfloat162_rn(n0, n1);
        __nv_bfloat162 p1 = __floats2bfloat162_rn(n2, n3);
        __nv_bfloat162 p2 = __floats2bfloat162_rn(n4, n5);
        __nv_bfloat162 p3 = __floats2bfloat162_rn(n6, n7);
        uint4 pk;
        pk.x = *reinterpret_cast<uint32_t*>(&p0);
        pk.y = *reinterpret_cast<uint32_t*>(&p1);
        pk.z = *reinterpret_cast<uint32_t*>(&p2);
        pk.w = *reinterpret_cast<uint32_t*>(&p3);
        reinterpret_cast<uint4*>(g_V)[(size_t)row * (D_ / 8) + lane] = pk;

        int s = 0;
        if (lane == 0) {
            float4 lb = reinterpret_cast<const float4*>(lab)[row];
            s = lb.y > 0.5f ? 1 : (lb.z > 0.5f ? 2 : (lb.w > 0.5f ? 3 : 0));
            g_cls[row] = (unsigned char)s;
        }
        s = __shfl_sync(0xffffffffu, s, 0);

        // warp-uniform branch, compile-time accumulator indices (register-safe)
        #define ACCUM(C) { acc[C][0]+=n0; acc[C][1]+=n1; acc[C][2]+=n2; acc[C][3]+=n3; \
                           acc[C][4]+=n4; acc[C][5]+=n5; acc[C][6]+=n6; acc[C][7]+=n7; }
        if      (s == 0) ACCUM(0)
        else if (s == 1) ACCUM(1)
        else if (s == 2) ACCUM(2)
        else             ACCUM(3)
        #undef ACCUM
    }

    // cross-warp reduce: sred[wid][(c*8+i)*32 + lane]  (conflict-free)
    #pragma unroll
    for (int c = 0; c < 4; c++)
        #pragma unroll
        for (int i = 0; i < 8; i++)
            sred[wid * 1024 + (c * 8 + i) * 32 + lane] = acc[c][i];
    __syncthreads();

    #pragma unroll
    for (int j = 0; j < 4; j++) {
        int o = threadIdx.x + 256 * j;   // o = v*32 + l, v = c*8+i
        float sum = 0.0f;
        #pragma unroll
        for (int w = 0; w < 8; w++) sum += sred[w * 1024 + o];
        int v = o >> 5, l = o & 31;
        int d = l * 8 + (v & 7), s = v >> 3;
        atomicAdd(g_Gvy + (b * D_ + d) * S_ + s, sum);
    }
}

// ---------------------------------------------------------------------------
// PTX helpers
// ---------------------------------------------------------------------------
__device__ __forceinline__ void cp16(__nv_bfloat16* dst, const __nv_bfloat16* src) {
    unsigned d = (unsigned)__cvta_generic_to_shared(dst);
    asm volatile("cp.async.cg.shared.global [%0], [%1], 16;\n" :: "r"(d), "l"(src));
}
__device__ __forceinline__ void cp_commit() { asm volatile("cp.async.commit_group;\n"); }
template <int N> __device__ __forceinline__ void cp_wait() {
    asm volatile("cp.async.wait_group %0;\n" :: "n"(N));
}
__device__ __forceinline__ void ldsm4t(uint32_t* r, const __nv_bfloat16* p) {
    unsigned a = (unsigned)__cvta_generic_to_shared(p);
    asm volatile("ldmatrix.sync.aligned.m8n8.x4.trans.shared.b16 {%0,%1,%2,%3}, [%4];\n"
                 : "=r"(r[0]), "=r"(r[1]), "=r"(r[2]), "=r"(r[3]) : "r"(a));
}
__device__ __forceinline__ void mma_bf16(float* c, const uint32_t* a, const uint32_t* b) {
    asm volatile("mma.sync.aligned.m16n8k16.row.col.f32.bf16.bf16.f32 "
                 "{%0,%1,%2,%3},{%4,%5,%6,%7},{%8,%9},{%0,%1,%2,%3};\n"
                 : "+f"(c[0]), "+f"(c[1]), "+f"(c[2]), "+f"(c[3])
                 : "r"(a[0]), "r"(a[1]), "r"(a[2]), "r"(a[3]), "r"(b[0]), "r"(b[1]));
}

// ---------------------------------------------------------------------------
// K2: Gram tiles Gvv = V^T V. grid.x = 48 (batch*3 + tile), grid.y = KSPLIT.
// ---------------------------------------------------------------------------
__global__ __launch_bounds__(256) void k_gram() {
    extern __shared__ __nv_bfloat16 sm[];
    int bt   = blockIdx.x;
    int b    = bt / 3, tile = bt % 3;
    int ti   = (tile == 0) ? 0 : 1;
    int tj   = (tile == 2) ? 1 : 0;
    bool diag = (ti == tj);
    int kc   = blockIdx.y;
    int tid  = threadIdx.x;
    const __nv_bfloat16* gv = g_V + (size_t)(b * T_ + kc * KCHUNK) * D_;

    int wid = tid >> 5, lane = tid & 31;
    int wm = (wid & 3) * 32;
    int wn = (wid >> 2) * 64;
    int q = lane >> 3, rr = lane & 7;

    float acc[2][8][4];
    #pragma unroll
    for (int mi = 0; mi < 2; mi++)
        #pragma unroll
        for (int ni = 0; ni < 8; ni++)
            #pragma unroll
            for (int x = 0; x < 4; x++) acc[mi][ni][x] = 0.0f;

    auto load_stage = [&](int st, int kofs) {
        const __nv_bfloat16* ga = gv + (size_t)kofs * D_ + ti * TILE;
        __nv_bfloat16* sa = sm + st * MS;
        #pragma unroll
        for (int i = 0; i < 4; i++) {
            int c = tid + i * 256;
            int r = c >> 4, cc = c & 15;
            cp16(sa + r * PITCH + cc * 8, ga + r * D_ + cc * 8);
        }
        if (!diag) {
            const __nv_bfloat16* gb = gv + (size_t)kofs * D_ + tj * TILE;
            __nv_bfloat16* sb = sm + (2 + st) * MS;
            #pragma unroll
            for (int i = 0; i < 4; i++) {
                int c = tid + i * 256;
                int r = c >> 4, cc = c & 15;
                cp16(sb + r * PITCH + cc * 8, gb + r * D_ + cc * 8);
            }
        }
        cp_commit();
    };

    load_stage(0, 0);
    const int NIT = KCHUNK / KT;  // 32
    for (int it = 0; it < NIT; ++it) {
        if (it + 1 < NIT) { load_stage((it + 1) & 1, (it + 1) * KT); cp_wait<1>(); }
        else              { cp_wait<0>(); }
        __syncthreads();
        const __nv_bfloat16* As = sm + (it & 1) * MS;
        const __nv_bfloat16* Bs = diag ? As : sm + (2 + (it & 1)) * MS;
        #pragma unroll
        for (int ks = 0; ks < KT / 16; ++ks) {
            uint32_t af[2][4];
            #pragma unroll
            for (int mi = 0; mi < 2; mi++) {
                int dm   = wm + mi * 16;
                int krow = ks * 16 + ((q & 2) ? 8 : 0) + rr;
                int col  = dm + ((q & 1) ? 8 : 0);
                ldsm4t(af[mi], As + krow * PITCH + col);
            }
            uint32_t bfr[8][2];
            #pragma unroll
            for (int j = 0; j < 4; j++) {
                int n0   = wn + j * 16;
                int krow = ks * 16 + ((q & 1) ? 8 : 0) + rr;
                int col  = n0 + ((q & 2) ? 8 : 0);
                uint32_t t4[4];
                ldsm4t(t4, Bs + krow * PITCH + col);
                bfr[2 * j][0]     = t4[0]; bfr[2 * j][1]     = t4[1];
                bfr[2 * j + 1][0] = t4[2]; bfr[2 * j + 1][1] = t4[3];
            }
            #pragma unroll
            for (int mi = 0; mi < 2; mi++)
                #pragma unroll
                for (int ni = 0; ni < 8; ni++)
                    mma_bf16(acc[mi][ni], af[mi], bfr[ni]);
        }
        __syncthreads();
    }

    // Epilogue: plain stores of this K-split's partial tile
    int gid = lane >> 2, tig = lane & 3;
    float* gdst = g_GvvP + ((size_t)bt * KSPLIT + kc) * TILE * TILE;
    #pragma unroll
    for (int mi = 0; mi < 2; mi++) {
        #pragma unroll
        for (int ni = 0; ni < 8; ni++) {
            int m = wm + mi * 16 + gid;
            int n = wn + ni * 8 + tig * 2;
            float* p = gdst + m * TILE + n;
            p[0] = acc[mi][ni][0];
            p[1] = acc[mi][ni][1];
            p[8 * TILE + 0] = acc[mi][ni][2];
            p[8 * TILE + 1] = acc[mi][ni][3];
        }
    }
}

// ---------------------------------------------------------------------------
// Reductions
// ---------------------------------------------------------------------------
__device__ float blockSum(float v) {
    __shared__ float sw[8];
    int lane = threadIdx.x & 31, w = threadIdx.x >> 5;
    __syncthreads();
    #pragma unroll
    for (int o = 16; o; o >>= 1) v += __shfl_xor_sync(0xffffffffu, v, o);
    if (lane == 0) sw[w] = v;
    __syncthreads();
    v = (threadIdx.x < 8) ? sw[threadIdx.x] : 0.0f;
    if (w == 0)
        #pragma unroll
        for (int o = 4; o; o >>= 1) v += __shfl_xor_sync(0xffu, v, o);
    return v;  // valid in thread 0
}

__global__ __launch_bounds__(256) void k_red1() {
    int bid = blockIdx.x, tid = threadIdx.x;
    if (bid < 48) {
        const float* g = g_GvvP + (size_t)bid * KSPLIT * TILE * TILE;
        float total = 0.0f;
        for (int i = tid; i < TILE * TILE; i += 256) {
            float x = 0.0f;
            #pragma unroll
            for (int kc = 0; kc < KSPLIT; kc++) x += g[kc * TILE * TILE + i];
            total += x * x;
        }
        total = blockSum(total);
        if (tid == 0) {
            float w = (bid % 3 == 1) ? 2.0f : 1.0f;  // off-diagonal tile counts twice
            g_part[bid] = w * total;
        }
    } else {
        int b = bid - 48;
        float gy = 0.0f;
        for (int i = tid; i < D_ * S_; i += 256) { float x = g_Gvy[b * D_ * S_ + i]; gy += x * x; }
        float c0 = 0, c1 = 0, c2 = 0, c3 = 0;
        for (int t = tid; t < T_; t += 256) {
            int s = g_cls[b * T_ + t];
            c0 += (s == 0); c1 += (s == 1); c2 += (s == 2); c3 += (s == 3);
        }
        gy = blockSum(gy);
        c0 = blockSum(c0); c1 = blockSum(c1); c2 = blockSum(c2); c3 = blockSum(c3);
        if (tid == 0)
            g_part[bid] = -2.0f * gy + c0 * c0 + c1 * c1 + c2 * c2 + c3 * c3;
    }
}

__global__ void k_final(float* out) {
    int tid = threadIdx.x;  // 64 threads
    float v = g_part[tid];
    #pragma unroll
    for (int o = 16; o; o >>= 1) v += __shfl_xor_sync(0xffffffffu, v, o);
    __shared__ float s2[2];
    if ((tid & 31) == 0) s2[tid >> 5] = v;
    __syncthreads();
    if (tid == 0) {
        float total = s2[0] + s2[1];
        // divide by T*T*B = 2^32 (exact power of two)
        out[0] = total * 2.3283064365386963e-10f;
    }
}

// ---------------------------------------------------------------------------
extern "C" void kernel_launch(void* const* d_in, const int* in_sizes, int n_in,
                              void* d_out, int out_size) {
    const float* emb = (const float*)d_in[0];
    const float* lab = (const float*)d_in[1];
    float* out = (float*)d_out;
    (void)in_sizes; (void)n_in; (void)out_size;

    const int smem_bytes = 4 * MS * (int)sizeof(__nv_bfloat16);  // 69632
    cudaFuncSetAttribute(k_gram, cudaFuncAttributeMaxDynamicSharedMemorySize, smem_bytes);

    k_zero<<<64, 256>>>();
    k_norm<<<512, 256>>>(emb, lab);   // fused normalize + Gvy
    dim3 g2(48, KSPLIT);
    k_gram<<<g2, 256, smem_bytes>>>();
    k_red1<<<64, 256>>>();
    k_final<<<1, 64>>>(out);
}

// round 4
// speedup vs baseline: 1.9507x; 1.0570x over previous
#include <cuda_runtime.h>
#include <cuda_bf16.h>
#include <cstdint>

// Problem constants
#define B_ 16
#define T_ 16384
#define D_ 256
#define S_ 4
#define TILE 128
#define KT 64
#define KSPLIT 3               // 48*3 = 144 CTAs = one wave on 148 SMs
#define NITER (T_ / KT)        // 256 total KT-iterations, split 86/85/85
#define PITCH 136              // 128 + 8 pad -> conflict-free ldmatrix.trans
#define MS (KT * PITCH)        // elements per smem matrix stage

// Scratch (device globals: allocation-free rule)
__device__ __nv_bfloat16 g_V[(size_t)B_ * T_ * D_];         // normalized V, bf16
__device__ unsigned char g_cls[B_ * T_];                     // speaker class per row
__device__ float g_GvvP[(size_t)48 * KSPLIT * TILE * TILE];  // K-split partials (9.4MB)
__device__ float g_Gvy[B_ * D_ * S_];
__device__ float g_acc[1];

// ---------------------------------------------------------------------------
// K0: zero atomic targets
// ---------------------------------------------------------------------------
__global__ void k_zero() {
    int i = blockIdx.x * 256 + threadIdx.x;
    if (i < B_ * D_ * S_) g_Gvy[i] = 0.0f;
    if (i == 0) g_acc[0] = 0.0f;
}

// ---------------------------------------------------------------------------
// K1: fused row-wise L2 normalize (fp32 -> bf16) + class extraction + Gvy
// accumulation. 512 blocks (32/batch), 8 warps, warp = 64 consecutive rows.
// ---------------------------------------------------------------------------
__global__ __launch_bounds__(256) void k_norm(const float* __restrict__ emb,
                                              const float* __restrict__ lab) {
    __shared__ float sred[8 * 1024];
    int b    = blockIdx.x >> 5;
    int ch   = blockIdx.x & 31;
    int wid  = threadIdx.x >> 5, lane = threadIdx.x & 31;
    int row0 = b * T_ + ch * 512 + wid * 64;

    float acc[4][8];
    #pragma unroll
    for (int c = 0; c < 4; c++)
        #pragma unroll
        for (int i = 0; i < 8; i++) acc[c][i] = 0.0f;

    #pragma unroll 2
    for (int r = 0; r < 64; ++r) {
        int row = row0 + r;
        const float4* src = reinterpret_cast<const float4*>(emb) + (size_t)row * (D_ / 4) + lane * 2;
        float4 v0 = src[0];
        float4 v1 = src[1];
        float ss = v0.x*v0.x + v0.y*v0.y + v0.z*v0.z + v0.w*v0.w
                 + v1.x*v1.x + v1.y*v1.y + v1.z*v1.z + v1.w*v1.w;
        #pragma unroll
        for (int o = 16; o; o >>= 1) ss += __shfl_xor_sync(0xffffffffu, ss, o);
        float sc = 1.0f / fmaxf(sqrtf(ss), 1e-12f);

        float n0 = v0.x * sc, n1 = v0.y * sc, n2 = v0.z * sc, n3 = v0.w * sc;
        float n4 = v1.x * sc, n5 = v1.y * sc, n6 = v1.z * sc, n7 = v1.w * sc;

        __nv_bfloat162 p0 = __floats2bfloat162_rn(n0, n1);
        __nv_bfloat162 p1 = __floats2bfloat162_rn(n2, n3);
        __nv_bfloat162 p2 = __floats2bfloat162_rn(n4, n5);
        __nv_bfloat162 p3 = __floats2bfloat162_rn(n6, n7);
        uint4 pk;
        pk.x = *reinterpret_cast<uint32_t*>(&p0);
        pk.y = *reinterpret_cast<uint32_t*>(&p1);
        pk.z = *reinterpret_cast<uint32_t*>(&p2);
        pk.w = *reinterpret_cast<uint32_t*>(&p3);
        reinterpret_cast<uint4*>(g_V)[(size_t)row * (D_ / 8) + lane] = pk;

        int s = 0;
        if (lane == 0) {
            float4 lb = reinterpret_cast<const float4*>(lab)[row];
            s = lb.y > 0.5f ? 1 : (lb.z > 0.5f ? 2 : (lb.w > 0.5f ? 3 : 0));
            g_cls[row] = (unsigned char)s;
        }
        s = __shfl_sync(0xffffffffu, s, 0);

        // warp-uniform branch, compile-time accumulator indices (register-safe)
        #define ACCUM(C) { acc[C][0]+=n0; acc[C][1]+=n1; acc[C][2]+=n2; acc[C][3]+=n3; \
                           acc[C][4]+=n4; acc[C][5]+=n5; acc[C][6]+=n6; acc[C][7]+=n7; }
        if      (s == 0) ACCUM(0)
        else if (s == 1) ACCUM(1)
        else if (s == 2) ACCUM(2)
        else             ACCUM(3)
        #undef ACCUM
    }

    // cross-warp reduce: sred[wid][(c*8+i)*32 + lane]  (conflict-free)
    #pragma unroll
    for (int c = 0; c < 4; c++)
        #pragma unroll
        for (int i = 0; i < 8; i++)
            sred[wid * 1024 + (c * 8 + i) * 32 + lane] = acc[c][i];
    __syncthreads();

    #pragma unroll
    for (int j = 0; j < 4; j++) {
        int o = threadIdx.x + 256 * j;   // o = v*32 + l, v = c*8+i
        float sum = 0.0f;
        #pragma unroll
        for (int w = 0; w < 8; w++) sum += sred[w * 1024 + o];
        int v = o >> 5, l = o & 31;
        int d = l * 8 + (v & 7), s = v >> 3;
        atomicAdd(g_Gvy + (b * D_ + d) * S_ + s, sum);
    }
}

// ---------------------------------------------------------------------------
// PTX helpers
// ---------------------------------------------------------------------------
__device__ __forceinline__ void cp16(__nv_bfloat16* dst, const __nv_bfloat16* src) {
    unsigned d = (unsigned)__cvta_generic_to_shared(dst);
    asm volatile("cp.async.cg.shared.global [%0], [%1], 16;\n" :: "r"(d), "l"(src));
}
__device__ __forceinline__ void cp_commit() { asm volatile("cp.async.commit_group;\n"); }
template <int N> __device__ __forceinline__ void cp_wait() {
    asm volatile("cp.async.wait_group %0;\n" :: "n"(N));
}
__device__ __forceinline__ void ldsm4t(uint32_t* r, const __nv_bfloat16* p) {
    unsigned a = (unsigned)__cvta_generic_to_shared(p);
    asm volatile("ldmatrix.sync.aligned.m8n8.x4.trans.shared.b16 {%0,%1,%2,%3}, [%4];\n"
                 : "=r"(r[0]), "=r"(r[1]), "=r"(r[2]), "=r"(r[3]) : "r"(a));
}
__device__ __forceinline__ void mma_bf16(float* c, const uint32_t* a, const uint32_t* b) {
    asm volatile("mma.sync.aligned.m16n8k16.row.col.f32.bf16.bf16.f32 "
                 "{%0,%1,%2,%3},{%4,%5,%6,%7},{%8,%9},{%0,%1,%2,%3};\n"
                 : "+f"(c[0]), "+f"(c[1]), "+f"(c[2]), "+f"(c[3])
                 : "r"(a[0]), "r"(a[1]), "r"(a[2]), "r"(a[3]), "r"(b[0]), "r"(b[1]));
}

// ---------------------------------------------------------------------------
// K2: Gram tiles Gvv = V^T V. grid.x = 48, grid.y = 3 (one wave: 144 CTAs).
// K-iterations split 86/85/85.
// ---------------------------------------------------------------------------
__global__ __launch_bounds__(256) void k_gram() {
    extern __shared__ __nv_bfloat16 sm[];
    int bt   = blockIdx.x;
    int b    = bt / 3, tile = bt % 3;
    int ti   = (tile == 0) ? 0 : 1;
    int tj   = (tile == 2) ? 1 : 0;
    bool diag = (ti == tj);
    int kc   = blockIdx.y;
    int it0  = kc * 85 + (kc > 0 ? 1 : 0);
    int NIT  = (kc == 0) ? 86 : 85;
    int tid  = threadIdx.x;
    const __nv_bfloat16* gv = g_V + (size_t)b * T_ * D_;

    int wid = tid >> 5, lane = tid & 31;
    int wm = (wid & 3) * 32;
    int wn = (wid >> 2) * 64;
    int q = lane >> 3, rr = lane & 7;

    float acc[2][8][4];
    #pragma unroll
    for (int mi = 0; mi < 2; mi++)
        #pragma unroll
        for (int ni = 0; ni < 8; ni++)
            #pragma unroll
            for (int x = 0; x < 4; x++) acc[mi][ni][x] = 0.0f;

    auto load_stage = [&](int st, int iter) {
        size_t kofs = (size_t)(it0 + iter) * KT;
        const __nv_bfloat16* ga = gv + kofs * D_ + ti * TILE;
        __nv_bfloat16* sa = sm + st * MS;
        #pragma unroll
        for (int i = 0; i < 4; i++) {
            int c = tid + i * 256;
            int r = c >> 4, cc = c & 15;
            cp16(sa + r * PITCH + cc * 8, ga + r * D_ + cc * 8);
        }
        if (!diag) {
            const __nv_bfloat16* gb = gv + kofs * D_ + tj * TILE;
            __nv_bfloat16* sb = sm + (2 + st) * MS;
            #pragma unroll
            for (int i = 0; i < 4; i++) {
                int c = tid + i * 256;
                int r = c >> 4, cc = c & 15;
                cp16(sb + r * PITCH + cc * 8, gb + r * D_ + cc * 8);
            }
        }
        cp_commit();
    };

    load_stage(0, 0);
    for (int it = 0; it < NIT; ++it) {
        if (it + 1 < NIT) { load_stage((it + 1) & 1, it + 1); cp_wait<1>(); }
        else              { cp_wait<0>(); }
        __syncthreads();
        const __nv_bfloat16* As = sm + (it & 1) * MS;
        const __nv_bfloat16* Bs = diag ? As : sm + (2 + (it & 1)) * MS;
        #pragma unroll
        for (int ks = 0; ks < KT / 16; ++ks) {
            uint32_t af[2][4];
            #pragma unroll
            for (int mi = 0; mi < 2; mi++) {
                int dm   = wm + mi * 16;
                int krow = ks * 16 + ((q & 2) ? 8 : 0) + rr;
                int col  = dm + ((q & 1) ? 8 : 0);
                ldsm4t(af[mi], As + krow * PITCH + col);
            }
            uint32_t bfr[8][2];
            #pragma unroll
            for (int j = 0; j < 4; j++) {
                int n0   = wn + j * 16;
                int krow = ks * 16 + ((q & 1) ? 8 : 0) + rr;
                int col  = n0 + ((q & 2) ? 8 : 0);
                uint32_t t4[4];
                ldsm4t(t4, Bs + krow * PITCH + col);
                bfr[2 * j][0]     = t4[0]; bfr[2 * j][1]     = t4[1];
                bfr[2 * j + 1][0] = t4[2]; bfr[2 * j + 1][1] = t4[3];
            }
            #pragma unroll
            for (int mi = 0; mi < 2; mi++)
                #pragma unroll
                for (int ni = 0; ni < 8; ni++)
                    mma_bf16(acc[mi][ni], af[mi], bfr[ni]);
        }
        __syncthreads();
    }

    // Epilogue: plain stores of this K-split's partial tile
    int gid = lane >> 2, tig = lane & 3;
    float* gdst = g_GvvP + ((size_t)bt * KSPLIT + kc) * TILE * TILE;
    #pragma unroll
    for (int mi = 0; mi < 2; mi++) {
        #pragma unroll
        for (int ni = 0; ni < 8; ni++) {
            int m = wm + mi * 16 + gid;
            int n = wn + ni * 8 + tig * 2;
            float* p = gdst + m * TILE + n;
            p[0] = acc[mi][ni][0];
            p[1] = acc[mi][ni][1];
            p[8 * TILE + 0] = acc[mi][ni][2];
            p[8 * TILE + 1] = acc[mi][ni][3];
        }
    }
}

// ---------------------------------------------------------------------------
// K3: parallel reduction. 208 blocks:
//   bid < 192: Gvv tile quarter -> sum 3 partials, square, weighted atomic
//   bid >= 192: per-batch Gvy^2 and class-count^2
// ---------------------------------------------------------------------------
__device__ float blockSum(float v) {
    __shared__ float sw[8];
    int lane = threadIdx.x & 31, w = threadIdx.x >> 5;
    __syncthreads();
    #pragma unroll
    for (int o = 16; o; o >>= 1) v += __shfl_xor_sync(0xffffffffu, v, o);
    if (lane == 0) sw[w] = v;
    __syncthreads();
    v = (threadIdx.x < 8) ? sw[threadIdx.x] : 0.0f;
    if (w == 0)
        #pragma unroll
        for (int o = 4; o; o >>= 1) v += __shfl_xor_sync(0xffu, v, o);
    return v;  // valid in thread 0
}

__global__ __launch_bounds__(256) void k_red() {
    int bid = blockIdx.x, tid = threadIdx.x;
    if (bid < 192) {
        int bt = bid >> 2, qd = bid & 3;
        const float* g = g_GvvP + (size_t)bt * KSPLIT * TILE * TILE + qd * 4096;
        float total = 0.0f;
        #pragma unroll 4
        for (int i = tid; i < 4096; i += 256) {
            float x = g[i] + g[KSPLIT ? (1 * TILE * TILE) : 0 ? 0 : 1 * TILE * TILE + i] ;
            // (expanded below properly)
            x = g[i] + g[1 * TILE * TILE + i] + g[2 * TILE * TILE + i];
            total += x * x;
        }
        total = blockSum(total);
        if (tid == 0) {
            float w = (bt % 3 == 1) ? 2.0f : 1.0f;  // off-diagonal tile counts twice
            atomicAdd(g_acc, w * total);
        }
    } else {
        int b = bid - 192;
        float gy = 0.0f;
        for (int i = tid; i < D_ * S_; i += 256) { float x = g_Gvy[b * D_ * S_ + i]; gy += x * x; }
        float c0 = 0, c1 = 0, c2 = 0, c3 = 0;
        for (int t = tid; t < T_; t += 256) {
            int s = g_cls[b * T_ + t];
            c0 += (s == 0); c1 += (s == 1); c2 += (s == 2); c3 += (s == 3);
        }
        gy = blockSum(gy);
        c0 = blockSum(c0); c1 = blockSum(c1); c2 = blockSum(c2); c3 = blockSum(c3);
        if (tid == 0)
            atomicAdd(g_acc, -2.0f * gy + c0 * c0 + c1 * c1 + c2 * c2 + c3 * c3);
    }
}

__global__ void k_final(float* out) {
    // divide by T*T*B = 2^32 (exact power of two)
    out[0] = g_acc[0] * 2.3283064365386963e-10f;
}

// ---------------------------------------------------------------------------
extern "C" void kernel_launch(void* const* d_in, const int* in_sizes, int n_in,
                              void* d_out, int out_size) {
    const float* emb = (const float*)d_in[0];
    const float* lab = (const float*)d_in[1];
    float* out = (float*)d_out;
    (void)in_sizes; (void)n_in; (void)out_size;

    const int smem_bytes = 4 * MS * (int)sizeof(__nv_bfloat16);  // 69632
    cudaFuncSetAttribute(k_gram, cudaFuncAttributeMaxDynamicSharedMemorySize, smem_bytes);

    k_zero<<<64, 256>>>();
    k_norm<<<512, 256>>>(emb, lab);   // fused normalize + Gvy
    dim3 g2(48, KSPLIT);
    k_gram<<<g2, 256, smem_bytes>>>();
    k_red<<<208, 256>>>();
    k_final<<<1, 1>>>(out);
}

// round 5
// speedup vs baseline: 2.1059x; 1.0796x over previous
#include <cuda_runtime.h>
#include <cuda_bf16.h>
#include <cstdint>

// Problem constants
#define B_ 16
#define T_ 16384
#define D_ 256
#define S_ 4
#define TILE 128
#define KT 64
#define KSPLIT 3               // 48*3 = 144 CTAs = one wave on 148 SMs
#define PITCH 136              // 128 + 8 pad -> conflict-free ldmatrix.trans
#define MS (KT * PITCH)        // elements per smem matrix stage
#define NSTAGE 4

// Scratch (device globals: allocation-free rule)
__device__ __nv_bfloat16 g_V[(size_t)B_ * T_ * D_];         // normalized V, bf16
__device__ unsigned char g_cls[B_ * T_];                     // speaker class per row
__device__ float g_GvvP[(size_t)48 * KSPLIT * TILE * TILE];  // K-split partials (9.4MB)
__device__ float g_Gvy[B_ * D_ * S_];
__device__ float g_acc[1];
__device__ unsigned int g_done;

// ---------------------------------------------------------------------------
// K0: zero atomic targets
// ---------------------------------------------------------------------------
__global__ void k_zero() {
    int i = blockIdx.x * 256 + threadIdx.x;
    if (i < B_ * D_ * S_) g_Gvy[i] = 0.0f;
    if (i == 0) { g_acc[0] = 0.0f; g_done = 0u; }
}

// ---------------------------------------------------------------------------
// K1: fused row-wise L2 normalize (fp32 -> bf16) + class extraction + Gvy
// accumulation. 512 blocks (32/batch), 8 warps, warp = 64 consecutive rows.
// ---------------------------------------------------------------------------
__global__ __launch_bounds__(256) void k_norm(const float* __restrict__ emb,
                                              const float* __restrict__ lab) {
    __shared__ float sred[8 * 1024];
    int b    = blockIdx.x >> 5;
    int ch   = blockIdx.x & 31;
    int wid  = threadIdx.x >> 5, lane = threadIdx.x & 31;
    int row0 = b * T_ + ch * 512 + wid * 64;

    // coalesced class pre-load: lane l handles rows row0+l and row0+32+l
    int s_lo, s_hi;
    {
        float4 lb = reinterpret_cast<const float4*>(lab)[row0 + lane];
        s_lo = lb.y > 0.5f ? 1 : (lb.z > 0.5f ? 2 : (lb.w > 0.5f ? 3 : 0));
        g_cls[row0 + lane] = (unsigned char)s_lo;
        float4 lb2 = reinterpret_cast<const float4*>(lab)[row0 + 32 + lane];
        s_hi = lb2.y > 0.5f ? 1 : (lb2.z > 0.5f ? 2 : (lb2.w > 0.5f ? 3 : 0));
        g_cls[row0 + 32 + lane] = (unsigned char)s_hi;
    }

    float acc[4][8];
    #pragma unroll
    for (int c = 0; c < 4; c++)
        #pragma unroll
        for (int i = 0; i < 8; i++) acc[c][i] = 0.0f;

    #pragma unroll 2
    for (int r = 0; r < 64; ++r) {
        int row = row0 + r;
        const float4* src = reinterpret_cast<const float4*>(emb) + (size_t)row * (D_ / 4) + lane * 2;
        float4 v0 = src[0];
        float4 v1 = src[1];
        float ss = v0.x*v0.x + v0.y*v0.y + v0.z*v0.z + v0.w*v0.w
                 + v1.x*v1.x + v1.y*v1.y + v1.z*v1.z + v1.w*v1.w;
        #pragma unroll
        for (int o = 16; o; o >>= 1) ss += __shfl_xor_sync(0xffffffffu, ss, o);
        float sc = 1.0f / fmaxf(sqrtf(ss), 1e-12f);

        float n0 = v0.x * sc, n1 = v0.y * sc, n2 = v0.z * sc, n3 = v0.w * sc;
        float n4 = v1.x * sc, n5 = v1.y * sc, n6 = v1.z * sc, n7 = v1.w * sc;

        __nv_bfloat162 p0 = __floats2bfloat162_rn(n0, n1);
        __nv_bfloat162 p1 = __floats2bfloat162_rn(n2, n3);
        __nv_bfloat162 p2 = __floats2bfloat162_rn(n4, n5);
        __nv_bfloat162 p3 = __floats2bfloat162_rn(n6, n7);
        uint4 pk;
        pk.x = *reinterpret_cast<uint32_t*>(&p0);
        pk.y = *reinterpret_cast<uint32_t*>(&p1);
        pk.z = *reinterpret_cast<uint32_t*>(&p2);
        pk.w = *reinterpret_cast<uint32_t*>(&p3);
        reinterpret_cast<uint4*>(g_V)[(size_t)row * (D_ / 8) + lane] = pk;

        int s = __shfl_sync(0xffffffffu, r < 32 ? s_lo : s_hi, r & 31);

        // warp-uniform branch, compile-time accumulator indices (register-safe)
        #define ACCUM(C) { acc[C][0]+=n0; acc[C][1]+=n1; acc[C][2]+=n2; acc[C][3]+=n3; \
                           acc[C][4]+=n4; acc[C][5]+=n5; acc[C][6]+=n6; acc[C][7]+=n7; }
        if      (s == 0) ACCUM(0)
        else if (s == 1) ACCUM(1)
        else if (s == 2) ACCUM(2)
        else             ACCUM(3)
        #undef ACCUM
    }

    // cross-warp reduce: sred[wid][(c*8+i)*32 + lane]  (conflict-free)
    #pragma unroll
    for (int c = 0; c < 4; c++)
        #pragma unroll
        for (int i = 0; i < 8; i++)
            sred[wid * 1024 + (c * 8 + i) * 32 + lane] = acc[c][i];
    __syncthreads();

    #pragma unroll
    for (int j = 0; j < 4; j++) {
        int o = threadIdx.x + 256 * j;   // o = v*32 + l, v = c*8+i
        float sum = 0.0f;
        #pragma unroll
        for (int w = 0; w < 8; w++) sum += sred[w * 1024 + o];
        int v = o >> 5, l = o & 31;
        int d = l * 8 + (v & 7), s = v >> 3;
        atomicAdd(g_Gvy + (b * D_ + d) * S_ + s, sum);
    }
}

// ---------------------------------------------------------------------------
// PTX helpers
// ---------------------------------------------------------------------------
__device__ __forceinline__ void cp16(__nv_bfloat16* dst, const __nv_bfloat16* src) {
    unsigned d = (unsigned)__cvta_generic_to_shared(dst);
    asm volatile("cp.async.cg.shared.global [%0], [%1], 16;\n" :: "r"(d), "l"(src));
}
__device__ __forceinline__ void cp_commit() { asm volatile("cp.async.commit_group;\n"); }
template <int N> __device__ __forceinline__ void cp_wait() {
    asm volatile("cp.async.wait_group %0;\n" :: "n"(N));
}
__device__ __forceinline__ void ldsm4t(uint32_t* r, const __nv_bfloat16* p) {
    unsigned a = (unsigned)__cvta_generic_to_shared(p);
    asm volatile("ldmatrix.sync.aligned.m8n8.x4.trans.shared.b16 {%0,%1,%2,%3}, [%4];\n"
                 : "=r"(r[0]), "=r"(r[1]), "=r"(r[2]), "=r"(r[3]) : "r"(a));
}
__device__ __forceinline__ void mma_bf16(float* c, const uint32_t* a, const uint32_t* b) {
    asm volatile("mma.sync.aligned.m16n8k16.row.col.f32.bf16.bf16.f32 "
                 "{%0,%1,%2,%3},{%4,%5,%6,%7},{%8,%9},{%0,%1,%2,%3};\n"
                 : "+f"(c[0]), "+f"(c[1]), "+f"(c[2]), "+f"(c[3])
                 : "r"(a[0]), "r"(a[1]), "r"(a[2]), "r"(a[3]), "r"(b[0]), "r"(b[1]));
}

// ---------------------------------------------------------------------------
// K2: Gram tiles Gvv = V^T V. grid.x = 48, grid.y = 3 (one wave: 144 CTAs).
// 4-stage cp.async pipeline, single __syncthreads per KT iteration.
// ---------------------------------------------------------------------------
__global__ __launch_bounds__(256) void k_gram() {
    extern __shared__ __nv_bfloat16 sm[];
    int bt   = blockIdx.x;
    int b    = bt / 3, tile = bt % 3;
    int ti   = (tile == 0) ? 0 : 1;
    int tj   = (tile == 2) ? 1 : 0;
    bool diag = (ti == tj);
    int kc   = blockIdx.y;
    int it0  = kc * 85 + (kc > 0 ? 1 : 0);
    int NIT  = (kc == 0) ? 86 : 85;
    int tid  = threadIdx.x;
    const __nv_bfloat16* gv = g_V + (size_t)b * T_ * D_;

    int wid = tid >> 5, lane = tid & 31;
    int wm = (wid & 3) * 32;
    int wn = (wid >> 2) * 64;
    int q = lane >> 3, rr = lane & 7;

    float acc[2][8][4];
    #pragma unroll
    for (int mi = 0; mi < 2; mi++)
        #pragma unroll
        for (int ni = 0; ni < 8; ni++)
            #pragma unroll
            for (int x = 0; x < 4; x++) acc[mi][ni][x] = 0.0f;

    auto load_stage = [&](int st, int iter) {
        size_t kofs = (size_t)(it0 + iter) * KT;
        const __nv_bfloat16* ga = gv + kofs * D_ + ti * TILE;
        __nv_bfloat16* sa = sm + st * MS;
        #pragma unroll
        for (int i = 0; i < 4; i++) {
            int c = tid + i * 256;
            int r = c >> 4, cc = c & 15;
            cp16(sa + r * PITCH + cc * 8, ga + r * D_ + cc * 8);
        }
        if (!diag) {
            const __nv_bfloat16* gb = gv + kofs * D_ + tj * TILE;
            __nv_bfloat16* sb = sm + (NSTAGE + st) * MS;
            #pragma unroll
            for (int i = 0; i < 4; i++) {
                int c = tid + i * 256;
                int r = c >> 4, cc = c & 15;
                cp16(sb + r * PITCH + cc * 8, gb + r * D_ + cc * 8);
            }
        }
    };

    // prologue: 3 stages in flight
    load_stage(0, 0); cp_commit();
    load_stage(1, 1); cp_commit();
    load_stage(2, 2); cp_commit();

    for (int it = 0; it < NIT; ++it) {
        cp_wait<2>();          // stage (it&3) landed
        __syncthreads();       // all warps done with stage being overwritten next
        if (it + 3 < NIT) load_stage((it + 3) & 3, it + 3);
        cp_commit();           // commit (possibly empty) keeps group accounting uniform

        int st = it & 3;
        const __nv_bfloat16* As = sm + st * MS;
        const __nv_bfloat16* Bs = diag ? As : sm + (NSTAGE + st) * MS;
        #pragma unroll
        for (int ks = 0; ks < KT / 16; ++ks) {
            uint32_t af[2][4];
            #pragma unroll
            for (int mi = 0; mi < 2; mi++) {
                int dm   = wm + mi * 16;
                int krow = ks * 16 + ((q & 2) ? 8 : 0) + rr;
                int col  = dm + ((q & 1) ? 8 : 0);
                ldsm4t(af[mi], As + krow * PITCH + col);
            }
            uint32_t bfr[8][2];
            #pragma unroll
            for (int j = 0; j < 4; j++) {
                int n0   = wn + j * 16;
                int krow = ks * 16 + ((q & 1) ? 8 : 0) + rr;
                int col  = n0 + ((q & 2) ? 8 : 0);
                uint32_t t4[4];
                ldsm4t(t4, Bs + krow * PITCH + col);
                bfr[2 * j][0]     = t4[0]; bfr[2 * j][1]     = t4[1];
                bfr[2 * j + 1][0] = t4[2]; bfr[2 * j + 1][1] = t4[3];
            }
            #pragma unroll
            for (int mi = 0; mi < 2; mi++)
                #pragma unroll
                for (int ni = 0; ni < 8; ni++)
                    mma_bf16(acc[mi][ni], af[mi], bfr[ni]);
        }
    }

    // Epilogue: plain stores of this K-split's partial tile
    int gid = lane >> 2, tig = lane & 3;
    float* gdst = g_GvvP + ((size_t)bt * KSPLIT + kc) * TILE * TILE;
    #pragma unroll
    for (int mi = 0; mi < 2; mi++) {
        #pragma unroll
        for (int ni = 0; ni < 8; ni++) {
            int m = wm + mi * 16 + gid;
            int n = wn + ni * 8 + tig * 2;
            float* p = gdst + m * TILE + n;
            p[0] = acc[mi][ni][0];
            p[1] = acc[mi][ni][1];
            p[8 * TILE + 0] = acc[mi][ni][2];
            p[8 * TILE + 1] = acc[mi][ni][3];
        }
    }
}

// ---------------------------------------------------------------------------
// K3: parallel reduction + final output (completion-counter pattern).
// 208 blocks: bid<192 -> Gvv quarters; bid>=192 -> per-batch Gvy^2 + counts.
// ---------------------------------------------------------------------------
__device__ float blockSum(float v) {
    __shared__ float sw[8];
    int lane = threadIdx.x & 31, w = threadIdx.x >> 5;
    __syncthreads();
    #pragma unroll
    for (int o = 16; o; o >>= 1) v += __shfl_xor_sync(0xffffffffu, v, o);
    if (lane == 0) sw[w] = v;
    __syncthreads();
    v = (threadIdx.x < 8) ? sw[threadIdx.x] : 0.0f;
    if (w == 0)
        #pragma unroll
        for (int o = 4; o; o >>= 1) v += __shfl_xor_sync(0xffu, v, o);
    return v;  // valid in thread 0
}

__global__ __launch_bounds__(256) void k_red(float* __restrict__ out) {
    int bid = blockIdx.x, tid = threadIdx.x;
    if (bid < 192) {
        int bt = bid >> 2, qd = bid & 3;
        const float* g = g_GvvP + (size_t)bt * KSPLIT * TILE * TILE + qd * 4096;
        float total = 0.0f;
        #pragma unroll 4
        for (int i = tid; i < 4096; i += 256) {
            float x = g[i] + g[1 * TILE * TILE + i] + g[2 * TILE * TILE + i];
            total += x * x;
        }
        total = blockSum(total);
        if (tid == 0) {
            float w = (bt % 3 == 1) ? 2.0f : 1.0f;  // off-diagonal tile counts twice
            atomicAdd(g_acc, w * total);
        }
    } else {
        int b = bid - 192;
        float gy = 0.0f;
        for (int i = tid; i < D_ * S_; i += 256) { float x = g_Gvy[b * D_ * S_ + i]; gy += x * x; }
        float c0 = 0, c1 = 0, c2 = 0, c3 = 0;
        for (int t = tid; t < T_; t += 256) {
            int s = g_cls[b * T_ + t];
            c0 += (s == 0); c1 += (s == 1); c2 += (s == 2); c3 += (s == 3);
        }
        gy = blockSum(gy);
        c0 = blockSum(c0); c1 = blockSum(c1); c2 = blockSum(c2); c3 = blockSum(c3);
        if (tid == 0)
            atomicAdd(g_acc, -2.0f * gy + c0 * c0 + c1 * c1 + c2 * c2 + c3 * c3);
    }
    // last block to finish writes the output
    if (tid == 0) {
        __threadfence();
        unsigned old = atomicAdd(&g_done, 1u);
        if (old == 207u) {
            // divide by T*T*B = 2^32 (exact power of two)
            out[0] = g_acc[0] * 2.3283064365386963e-10f;
        }
    }
}

// ---------------------------------------------------------------------------
extern "C" void kernel_launch(void* const* d_in, const int* in_sizes, int n_in,
                              void* d_out, int out_size) {
    const float* emb = (const float*)d_in[0];
    const float* lab = (const float*)d_in[1];
    float* out = (float*)d_out;
    (void)in_sizes; (void)n_in; (void)out_size;

    const int smem_bytes = 2 * NSTAGE * MS * (int)sizeof(__nv_bfloat16);  // 139264
    cudaFuncSetAttribute(k_gram, cudaFuncAttributeMaxDynamicSharedMemorySize, smem_bytes);

    k_zero<<<64, 256>>>();
    k_norm<<<512, 256>>>(emb, lab);   // fused normalize + Gvy
    dim3 g2(48, KSPLIT);
    k_gram<<<g2, 256, smem_bytes>>>();
    k_red<<<208, 256>>>(out);
}

// round 7
// speedup vs baseline: 2.3183x; 1.1009x over previous
#include <cuda_runtime.h>
#include <cuda_bf16.h>
#include <cstdint>

// Problem constants
#define B_ 16
#define T_ 16384
#define D_ 256
#define S_ 4
#define TILE 128
#define KT 64
#define KSPLIT 6               // 48*6 = 288 CTAs = 2 per SM
#define PITCH 136              // 128 + 8 pad -> conflict-free ldmatrix.trans
#define MS (KT * PITCH)        // elements per smem matrix stage
#define NSTAGE 2

// Scratch (device globals: allocation-free rule)
__device__ __nv_bfloat16 g_V[(size_t)B_ * T_ * D_];         // normalized V, bf16
__device__ unsigned char g_cls[B_ * T_];                     // speaker class per row
__device__ float g_GvvP[(size_t)48 * KSPLIT * TILE * TILE];  // K-split partials (18.9MB)
__device__ float g_Gvy[B_ * D_ * S_];
__device__ float g_acc[1];
__device__ unsigned int g_done;

// ---------------------------------------------------------------------------
// K0: zero atomic targets
// ---------------------------------------------------------------------------
__global__ void k_zero() {
    int i = blockIdx.x * 256 + threadIdx.x;
    if (i < B_ * D_ * S_) g_Gvy[i] = 0.0f;
    if (i == 0) { g_acc[0] = 0.0f; g_done = 0u; }
}

// ---------------------------------------------------------------------------
// K1: fused row-wise L2 normalize (fp32 -> bf16) + class extraction + Gvy
// accumulation. 512 blocks (32/batch), 8 warps, warp = 64 consecutive rows.
// ---------------------------------------------------------------------------
__global__ __launch_bounds__(256) void k_norm(const float* __restrict__ emb,
                                              const float* __restrict__ lab) {
    __shared__ float sred[8 * 1024];
    int b    = blockIdx.x >> 5;
    int ch   = blockIdx.x & 31;
    int wid  = threadIdx.x >> 5, lane = threadIdx.x & 31;
    int row0 = b * T_ + ch * 512 + wid * 64;

    // coalesced class pre-load: lane l handles rows row0+l and row0+32+l
    int s_lo, s_hi;
    {
        float4 lb = reinterpret_cast<const float4*>(lab)[row0 + lane];
        s_lo = lb.y > 0.5f ? 1 : (lb.z > 0.5f ? 2 : (lb.w > 0.5f ? 3 : 0));
        g_cls[row0 + lane] = (unsigned char)s_lo;
        float4 lb2 = reinterpret_cast<const float4*>(lab)[row0 + 32 + lane];
        s_hi = lb2.y > 0.5f ? 1 : (lb2.z > 0.5f ? 2 : (lb2.w > 0.5f ? 3 : 0));
        g_cls[row0 + 32 + lane] = (unsigned char)s_hi;
    }

    float acc[4][8];
    #pragma unroll
    for (int c = 0; c < 4; c++)
        #pragma unroll
        for (int i = 0; i < 8; i++) acc[c][i] = 0.0f;

    #pragma unroll 2
    for (int r = 0; r < 64; ++r) {
        int row = row0 + r;
        const float4* src = reinterpret_cast<const float4*>(emb) + (size_t)row * (D_ / 4) + lane * 2;
        float4 v0 = src[0];
        float4 v1 = src[1];
        float ss = v0.x*v0.x + v0.y*v0.y + v0.z*v0.z + v0.w*v0.w
                 + v1.x*v1.x + v1.y*v1.y + v1.z*v1.z + v1.w*v1.w;
        #pragma unroll
        for (int o = 16; o; o >>= 1) ss += __shfl_xor_sync(0xffffffffu, ss, o);
        float sc = 1.0f / fmaxf(sqrtf(ss), 1e-12f);

        float n0 = v0.x * sc, n1 = v0.y * sc, n2 = v0.z * sc, n3 = v0.w * sc;
        float n4 = v1.x * sc, n5 = v1.y * sc, n6 = v1.z * sc, n7 = v1.w * sc;

        __nv_bfloat162 p0 = __floats2bfloat162_rn(n0, n1);
        __nv_bfloat162 p1 = __floats2bfloat162_rn(n2, n3);
        __nv_bfloat162 p2 = __floats2bfloat162_rn(n4, n5);
        __nv_bfloat162 p3 = __floats2bfloat162_rn(n6, n7);
        uint4 pk;
        pk.x = *reinterpret_cast<uint32_t*>(&p0);
        pk.y = *reinterpret_cast<uint32_t*>(&p1);
        pk.z = *reinterpret_cast<uint32_t*>(&p2);
        pk.w = *reinterpret_cast<uint32_t*>(&p3);
        reinterpret_cast<uint4*>(g_V)[(size_t)row * (D_ / 8) + lane] = pk;

        int s = __shfl_sync(0xffffffffu, r < 32 ? s_lo : s_hi, r & 31);

        // warp-uniform branch, compile-time accumulator indices (register-safe)
        #define ACCUM(C) { acc[C][0]+=n0; acc[C][1]+=n1; acc[C][2]+=n2; acc[C][3]+=n3; \
                           acc[C][4]+=n4; acc[C][5]+=n5; acc[C][6]+=n6; acc[C][7]+=n7; }
        if      (s == 0) ACCUM(0)
        else if (s == 1) ACCUM(1)
        else if (s == 2) ACCUM(2)
        else             ACCUM(3)
        #undef ACCUM
    }

    // cross-warp reduce: sred[wid][(c*8+i)*32 + lane]  (conflict-free)
    #pragma unroll
    for (int c = 0; c < 4; c++)
        #pragma unroll
        for (int i = 0; i < 8; i++)
            sred[wid * 1024 + (c * 8 + i) * 32 + lane] = acc[c][i];
    __syncthreads();

    #pragma unroll
    for (int j = 0; j < 4; j++) {
        int o = threadIdx.x + 256 * j;   // o = v*32 + l, v = c*8+i
        float sum = 0.0f;
        #pragma unroll
        for (int w = 0; w < 8; w++) sum += sred[w * 1024 + o];
        int v = o >> 5, l = o & 31;
        int d = l * 8 + (v & 7), s = v >> 3;
        atomicAdd(g_Gvy + (b * D_ + d) * S_ + s, sum);
    }
}

// ---------------------------------------------------------------------------
// PTX helpers
// ---------------------------------------------------------------------------
__device__ __forceinline__ void cp16(__nv_bfloat16* dst, const __nv_bfloat16* src) {
    unsigned d = (unsigned)__cvta_generic_to_shared(dst);
    asm volatile("cp.async.cg.shared.global [%0], [%1], 16;\n" :: "r"(d), "l"(src));
}
__device__ __forceinline__ void cp_commit() { asm volatile("cp.async.commit_group;\n"); }
template <int N> __device__ __forceinline__ void cp_wait() {
    asm volatile("cp.async.wait_group %0;\n" :: "n"(N));
}
__device__ __forceinline__ void ldsm4t(uint32_t* r, const __nv_bfloat16* p) {
    unsigned a = (unsigned)__cvta_generic_to_shared(p);
    asm volatile("ldmatrix.sync.aligned.m8n8.x4.trans.shared.b16 {%0,%1,%2,%3}, [%4];\n"
                 : "=r"(r[0]), "=r"(r[1]), "=r"(r[2]), "=r"(r[3]) : "r"(a));
}
__device__ __forceinline__ void mma_bf16(float* c, const uint32_t* a, const uint32_t* b) {
    asm volatile("mma.sync.aligned.m16n8k16.row.col.f32.bf16.bf16.f32 "
                 "{%0,%1,%2,%3},{%4,%5,%6,%7},{%8,%9},{%0,%1,%2,%3};\n"
                 : "+f"(c[0]), "+f"(c[1]), "+f"(c[2]), "+f"(c[3])
                 : "r"(a[0]), "r"(a[1]), "r"(a[2]), "r"(a[3]), "r"(b[0]), "r"(b[1]));
}

// ---------------------------------------------------------------------------
// K2: Gram tiles Gvv = V^T V. grid (48, 6) = 288 CTAs = 2/SM for latency
// hiding on the legacy HMMA pipe. 2-stage ring, ONE __syncthreads per iter:
// wait(load it) -> sync -> issue load(it+1) -> compute(it).
// K-iterations: 43,43,43,43,42,42 (sum 256).
// ---------------------------------------------------------------------------
__global__ __launch_bounds__(256, 2) void k_gram() {
    extern __shared__ __nv_bfloat16 sm[];
    int bt   = blockIdx.x;
    int b    = bt / 3, tile = bt % 3;
    int ti   = (tile == 0) ? 0 : 1;
    int tj   = (tile == 2) ? 1 : 0;
    bool diag = (ti == tj);
    int kc   = blockIdx.y;
    int it0  = (kc < 4) ? 43 * kc : 172 + 42 * (kc - 4);
    int NIT  = (kc < 4) ? 43 : 42;
    int tid  = threadIdx.x;
    const __nv_bfloat16* gv = g_V + (size_t)b * T_ * D_;

    int wid = tid >> 5, lane = tid & 31;
    int wm = (wid & 3) * 32;
    int wn = (wid >> 2) * 64;
    int q = lane >> 3, rr = lane & 7;

    float acc[2][8][4];
    #pragma unroll
    for (int mi = 0; mi < 2; mi++)
        #pragma unroll
        for (int ni = 0; ni < 8; ni++)
            #pragma unroll
            for (int x = 0; x < 4; x++) acc[mi][ni][x] = 0.0f;

    auto load_stage = [&](int st, int iter) {
        size_t kofs = (size_t)(it0 + iter) * KT;
        const __nv_bfloat16* ga = gv + kofs * D_ + ti * TILE;
        __nv_bfloat16* sa = sm + st * MS;
        #pragma unroll
        for (int i = 0; i < 4; i++) {
            int c = tid + i * 256;
            int r = c >> 4, cc = c & 15;
            cp16(sa + r * PITCH + cc * 8, ga + r * D_ + cc * 8);
        }
        if (!diag) {
            const __nv_bfloat16* gb = gv + kofs * D_ + tj * TILE;
            __nv_bfloat16* sb = sm + (NSTAGE + st) * MS;
            #pragma unroll
            for (int i = 0; i < 4; i++) {
                int c = tid + i * 256;
                int r = c >> 4, cc = c & 15;
                cp16(sb + r * PITCH + cc * 8, gb + r * D_ + cc * 8);
            }
        }
        cp_commit();
    };

    load_stage(0, 0);

    for (int it = 0; it < NIT; ++it) {
        cp_wait<0>();          // stage (it&1) landed
        __syncthreads();       // all warps past compute(it-1): stage (it+1)&1 free
        if (it + 1 < NIT) load_stage((it + 1) & 1, it + 1);

        int st = it & 1;
        const __nv_bfloat16* As = sm + st * MS;
        const __nv_bfloat16* Bs = diag ? As : sm + (NSTAGE + st) * MS;
        #pragma unroll
        for (int ks = 0; ks < KT / 16; ++ks) {
            uint32_t af[2][4];
            #pragma unroll
            for (int mi = 0; mi < 2; mi++) {
                int dm   = wm + mi * 16;
                int krow = ks * 16 + ((q & 2) ? 8 : 0) + rr;
                int col  = dm + ((q & 1) ? 8 : 0);
                ldsm4t(af[mi], As + krow * PITCH + col);
            }
            uint32_t bfr[8][2];
            #pragma unroll
            for (int j = 0; j < 4; j++) {
                int n0   = wn + j * 16;
                int krow = ks * 16 + ((q & 1) ? 8 : 0) + rr;
                int col  = n0 + ((q & 2) ? 8 : 0);
                uint32_t t4[4];
                ldsm4t(t4, Bs + krow * PITCH + col);
                bfr[2 * j][0]     = t4[0]; bfr[2 * j][1]     = t4[1];
                bfr[2 * j + 1][0] = t4[2]; bfr[2 * j + 1][1] = t4[3];
            }
            #pragma unroll
            for (int mi = 0; mi < 2; mi++)
                #pragma unroll
                for (int ni = 0; ni < 8; ni++)
                    mma_bf16(acc[mi][ni], af[mi], bfr[ni]);
        }
    }

    // Epilogue: plain stores of this K-split's partial tile
    int gid = lane >> 2, tig = lane & 3;
    float* gdst = g_GvvP + ((size_t)bt * KSPLIT + kc) * TILE * TILE;
    #pragma unroll
    for (int mi = 0; mi < 2; mi++) {
        #pragma unroll
        for (int ni = 0; ni < 8; ni++) {
            int m = wm + mi * 16 + gid;
            int n = wn + ni * 8 + tig * 2;
            float* p = gdst + m * TILE + n;
            p[0] = acc[mi][ni][0];
            p[1] = acc[mi][ni][1];
            p[8 * TILE + 0] = acc[mi][ni][2];
            p[8 * TILE + 1] = acc[mi][ni][3];
        }
    }
}

// ---------------------------------------------------------------------------
// K3: parallel reduction + final output (completion-counter pattern).
// 208 blocks: bid<192 -> Gvv quarters (sum 6 partials); bid>=192 -> per-batch
// Gvy^2 + class-count^2.
// ---------------------------------------------------------------------------
__device__ float blockSum(float v) {
    __shared__ float sw[8];
    int lane = threadIdx.x & 31, w = threadIdx.x >> 5;
    __syncthreads();
    #pragma unroll
    for (int o = 16; o; o >>= 1) v += __shfl_xor_sync(0xffffffffu, v, o);
    if (lane == 0) sw[w] = v;
    __syncthreads();
    v = (threadIdx.x < 8) ? sw[threadIdx.x] : 0.0f;
    if (w == 0)
        #pragma unroll
        for (int o = 4; o; o >>= 1) v += __shfl_xor_sync(0xffu, v, o);
    return v;  // valid in thread 0
}

__global__ __launch_bounds__(256) void k_red(float* __restrict__ out) {
    int bid = blockIdx.x, tid = threadIdx.x;
    if (bid < 192) {
        int bt = bid >> 2, qd = bid & 3;
        const float* g = g_GvvP + (size_t)bt * KSPLIT * TILE * TILE + qd * 4096;
        float total = 0.0f;
        #pragma unroll 2
        for (int i = tid; i < 4096; i += 256) {
            float x = 0.0f;
            #pragma unroll
            for (int kc = 0; kc < KSPLIT; kc++) x += g[kc * TILE * TILE + i];
            total += x * x;
        }
        total = blockSum(total);
        if (tid == 0) {
            float w = (bt % 3 == 1) ? 2.0f : 1.0f;  // off-diagonal tile counts twice
            atomicAdd(g_acc, w * total);
        }
    } else {
        int b = bid - 192;
        float gy = 0.0f;
        for (int i = tid; i < D_ * S_; i += 256) { float x = g_Gvy[b * D_ * S_ + i]; gy += x * x; }
        float c0 = 0, c1 = 0, c2 = 0, c3 = 0;
        for (int t = tid; t < T_; t += 256) {
            int s = g_cls[b * T_ + t];
            c0 += (s == 0); c1 += (s == 1); c2 += (s == 2); c3 += (s == 3);
        }
        gy = blockSum(gy);
        c0 = blockSum(c0); c1 = blockSum(c1); c2 = blockSum(c2); c3 = blockSum(c3);
        if (tid == 0)
            atomicAdd(g_acc, -2.0f * gy + c0 * c0 + c1 * c1 + c2 * c2 + c3 * c3);
    }
    // last block to finish writes the output
    if (tid == 0) {
        __threadfence();
        unsigned old = atomicAdd(&g_done, 1u);
        if (old == 207u) {
            // divide by T*T*B = 2^32 (exact power of two)
            out[0] = g_acc[0] * 2.3283064365386963e-10f;
        }
    }
}

// ---------------------------------------------------------------------------
extern "C" void kernel_launch(void* const* d_in, const int* in_sizes, int n_in,
                              void* d_out, int out_size) {
    const float* emb = (const float*)d_in[0];
    const float* lab = (const float*)d_in[1];
    float* out = (float*)d_out;
    (void)in_sizes; (void)n_in; (void)out_size;

    const int smem_bytes = 2 * NSTAGE * MS * (int)sizeof(__nv_bfloat16);  // 69632
    cudaFuncSetAttribute(k_gram, cudaFuncAttributeMaxDynamicSharedMemorySize, smem_bytes);

    k_zero<<<64, 256>>>();
    k_norm<<<512, 256>>>(emb, lab);   // fused normalize + Gvy
    dim3 g2(48, KSPLIT);
    k_gram<<<g2, 256, smem_bytes>>>();
    k_red<<<208, 256>>>(out);
}